// round 8
// baseline (speedup 1.0000x reference)
#include <cuda_runtime.h>
#include <cuda_fp16.h>
#include <cstdint>

// ---------------- problem constants ----------------
#define NB      2
#define NATOMS  25000
#define NE      400000
#define DCH     128
#define NRBF    64
#define CUTOFF  15.0f
#define TABN    8192

#define TILE_E       128
#define NTILES_PER_B (NE / TILE_E)       // 3125 exact
#define NTILES       (NB * NTILES_PER_B) // 6250
#define GRID         148
#define TPB          256

// distance -> h1 lookup table (f32): h1(d) = ssp(rbf(d)@W1 + b1)
__device__ float  g_table[(TABN + 1) * DCH];    // ~4.2 MB, L2-resident
// W2 packed for MMA-B: g_w2h[c*128 + k] = (half)W2[k][c]
__device__ __half g_w2h[DCH * DCH];             // 32 KB

// ---------------- smem layout (bytes) ----------------
#define BP      272                      // f16 tile row pitch (256B data + 16B pad)
#define FPITCH  130                      // F row pitch in floats (EVEN: float2 stores)
#define SM_W2   0                        // 128*272 = 34816 : W2 [c][k] f16
#define SM_BT   34816                    // 128*272 = 34816 : h1 tile [e][k] f16
#define SM_F    69632                    // 128*130*4 = 66560 : F [e][c] f32
#define SM_DIST 136192                   // 512
#define SM_IDX  136704                   // 512
#define SM_SEG  137216                   // 512
#define SMEM_BYTES 137728

// ---------------- helpers ----------------
__device__ __forceinline__ uint32_t smem_u32(const void* p) {
    uint32_t a;
    asm("{ .reg .u64 t; cvta.to.shared.u64 t, %1; cvt.u32.u64 %0, t; }" : "=r"(a) : "l"(p));
    return a;
}
// pack two f32 -> f16x2 (lo = x, hi = y)
__device__ __forceinline__ uint32_t pack_half2(float x, float y) {
    uint32_t u;
    asm("cvt.rn.f16x2.f32 %0, %1, %2;" : "=r"(u) : "f"(y), "f"(x));
    return u;
}
__device__ __forceinline__ void ldmat_x4(uint32_t& r0, uint32_t& r1, uint32_t& r2, uint32_t& r3,
                                         uint32_t addr) {
    asm volatile("ldmatrix.sync.aligned.m8n8.x4.shared.b16 {%0,%1,%2,%3}, [%4];"
                 : "=r"(r0), "=r"(r1), "=r"(r2), "=r"(r3) : "r"(addr));
}
__device__ __forceinline__ void mma16816(float* d, uint32_t a0, uint32_t a1, uint32_t a2, uint32_t a3,
                                         uint32_t b0, uint32_t b1) {
    asm volatile("mma.sync.aligned.m16n8k16.row.col.f32.f16.f16.f32 "
                 "{%0,%1,%2,%3}, {%4,%5,%6,%7}, {%8,%9}, {%0,%1,%2,%3};"
                 : "+f"(d[0]), "+f"(d[1]), "+f"(d[2]), "+f"(d[3])
                 : "r"(a0), "r"(a1), "r"(a2), "r"(a3), "r"(b0), "r"(b1));
}
__device__ __forceinline__ float ssp(float x) {
    float ax = fabsf(x);
    return fmaxf(x, 0.f) + __logf(1.f + __expf(-ax)) - 0.69314718056f;
}

// ---------------- prologue 1: h1(d) table (f32) ----------------
__global__ void build_table_kernel(const float* __restrict__ centers,
                                   const float* __restrict__ gammav,
                                   const float* __restrict__ W1,
                                   const float* __restrict__ b1) {
    __shared__ float rbf[NRBF];
    const int i = blockIdx.x;
    const int c = threadIdx.x;
    const float x = (float)i * (CUTOFF / (float)TABN);
    if (c < NRBF) {
        float t = x - centers[c];
        rbf[c] = __expf(-gammav[c] * t * t);
    }
    __syncthreads();
    float acc = b1[c];
    #pragma unroll
    for (int k = 0; k < NRBF; k++)
        acc = fmaf(rbf[k], W1[k * DCH + c], acc);
    g_table[i * DCH + c] = ssp(acc);
}

// ---------------- prologue 2: W2 -> f16 [c][k] ----------------
__global__ void build_w2_kernel(const float* __restrict__ W2) {
    const int c = blockIdx.x;
    const int k = threadIdx.x;
    g_w2h[c * DCH + k] = __float2half(W2[k * DCH + c]);
}

// ---------------- main fused kernel ----------------
__global__ __launch_bounds__(TPB, 1)
void cfconv_mma_kernel(const float* __restrict__ atom,   // [B, N, D]
                       const float* __restrict__ dist,   // [B, E]
                       const int*   __restrict__ idx_j,  // [E]
                       const int*   __restrict__ seg_i,  // [E] sorted
                       const float* __restrict__ b2,     // [D]
                       float*       __restrict__ out)    // [B, N, D] zeroed
{
    extern __shared__ char smem[];
    const uint32_t sb   = smem_u32(smem);
    const int tid  = threadIdx.x;
    const int wid  = tid >> 5;
    const int lane = tid & 31;

    // ---- load W2 f16 tile into padded smem (coalesced, one-time) ----
    for (int i = tid; i < DCH * 16; i += TPB) {         // 2048 uint4
        const int c = i >> 4, j = i & 15;
        *(uint4*)(smem + SM_W2 + c * BP + j * 16) =
            *(const uint4*)((const char*)g_w2h + (c * DCH + j * 8) * 2);
    }

    float* dist_s = (float*)(smem + SM_DIST);
    int*   idx_s  = (int*)(smem + SM_IDX);
    int*   seg_s  = (int*)(smem + SM_SEG);
    float* Fs     = (float*)(smem + SM_F);

    // epilogue mapping: lane owns channel, streams ordered edges
    const int   ec   = 32 * (wid & 3) + lane;   // channel
    const int   half = wid >> 2;                // edge half: 0->0-63, 1->64-127
    const float b2c  = b2[ec];
    const float inv_h = (float)TABN / CUTOFF;

    // ldmatrix source addresses (per-lane, loop-invariant parts)
    const int e_base = wid * 16;
    // A (h1) frag rows: e = e_base + (lane&7) + ((lane>>3)&1)*8 ; kblk 16B select by lane>>4
    const uint32_t a_row  = (uint32_t)(e_base + (lane & 7) + ((lane >> 3) & 1) * 8);
    const uint32_t a_addr0 = sb + SM_BT + a_row * BP + ((lane >> 4) & 1) * 16;
    // B (W2) frag rows: n = (lane&7) + ((lane>>4)&1)*8 ; kblk 16B select by (lane>>3)&1
    const uint32_t b_row  = (uint32_t)((lane & 7) + ((lane >> 4) & 1) * 8);
    const uint32_t b_addr0 = sb + SM_W2 + b_row * BP + ((lane >> 3) & 1) * 16;

    for (int T = blockIdx.x; T < NTILES; T += GRID) {
        const int b   = T / NTILES_PER_B;
        const int tib = T % NTILES_PER_B;
        const long e0 = (long)tib * TILE_E;

        __syncthreads();   // previous tile's epilogue done with idx/seg/F

        // ---- stage per-tile scalars ----
        if (tid < TILE_E) {
            dist_s[tid] = dist[(size_t)b * NE + e0 + tid];
            idx_s[tid]  = idx_j[e0 + tid];
            seg_s[tid]  = seg_i[e0 + tid];
        }
        __syncthreads();

        // ---- build A tile: h1 via LUT lerp -> f16 [e][k] ----
        {
            const int e  = tid >> 1;
            const int kh = (tid & 1) * 64;
            float x = dist_s[e] * inv_h;
            int   i = (int)x;
            i = i < 0 ? 0 : (i > TABN - 1 ? TABN - 1 : i);
            const float f = x - (float)i;
            const float* rlo = g_table + (size_t)i * DCH + kh;
            const float* rhi = rlo + DCH;
            char* dst = smem + SM_BT + e * BP + kh * 2;
            #pragma unroll
            for (int k4 = 0; k4 < 64; k4 += 4) {
                const float4 lo = *(const float4*)(rlo + k4);
                const float4 hi = *(const float4*)(rhi + k4);
                uint2 u;
                u.x = pack_half2(fmaf(f, hi.x - lo.x, lo.x),
                                 fmaf(f, hi.y - lo.y, lo.y));
                u.y = pack_half2(fmaf(f, hi.z - lo.z, lo.z),
                                 fmaf(f, hi.w - lo.w, lo.w));
                *(uint2*)(dst + k4 * 2) = u;
            }
        }
        __syncthreads();

        // ---- GEMM: F[e][c] = sum_k h1[e][k] * W2[k][c]  (fp16 MMA, f32 accum) ----
        {
            float acc[16][4];
            #pragma unroll
            for (int t = 0; t < 16; t++)
                acc[t][0] = acc[t][1] = acc[t][2] = acc[t][3] = 0.f;

            #pragma unroll
            for (int s = 0; s < 8; s++) {                  // K = 8 steps of 16
                uint32_t a0, a1, a2, a3;
                ldmat_x4(a0, a1, a2, a3, a_addr0 + s * 32);
                #pragma unroll
                for (int t2 = 0; t2 < 8; t2++) {           // 2 n-tiles per ldmatrix
                    uint32_t b0, b1, b2r, b3;
                    ldmat_x4(b0, b1, b2r, b3, b_addr0 + (2 * t2) * 8 * BP + s * 32);
                    mma16816(acc[2 * t2],     a0, a1, a2, a3, b0,  b1);
                    mma16816(acc[2 * t2 + 1], a0, a1, a2, a3, b2r, b3);
                }
            }

            // store fragments -> F[e][c]
            const int er = e_base + lane / 4;
            const int cc = 2 * (lane & 3);
            #pragma unroll
            for (int t = 0; t < 16; t++) {
                const int cn = 8 * t + cc;
                *(float2*)(Fs + er * FPITCH + cn)       = make_float2(acc[t][0], acc[t][1]);
                *(float2*)(Fs + (er + 8) * FPITCH + cn) = make_float2(acc[t][2], acc[t][3]);
            }
        }
        __syncthreads();

        // ---- epilogue: +b2, ssp, gather, multiply, run-length scatter ----
        {
            const float* atomb = atom + (size_t)b * NATOMS * DCH;
            float*       outb  = out  + (size_t)b * NATOMS * DCH;
            int   cur = -1;
            float acc = 0.f;
            const int eb = half * 64;
            #pragma unroll 4
            for (int j = 0; j < 64; j++) {
                const int   el   = eb + j;
                const float filt = ssp(Fs[el * FPITCH + ec] + b2c);
                const int   aj   = idx_s[el];
                const int   sg   = seg_s[el];
                const float msg  = atomb[(size_t)aj * DCH + ec] * filt;
                if (sg != cur) {
                    if (cur >= 0) atomicAdd(outb + (size_t)cur * DCH + ec, acc);
                    cur = sg;
                    acc = msg;
                } else {
                    acc += msg;
                }
            }
            if (cur >= 0) atomicAdd(outb + (size_t)cur * DCH + ec, acc);
        }
    }
}

// ---------------- launch ----------------
extern "C" void kernel_launch(void* const* d_in, const int* in_sizes, int n_in,
                              void* d_out, int out_size) {
    const float* atom    = (const float*)d_in[0];
    const float* dist    = (const float*)d_in[1];
    const int*   idx_j   = (const int*)  d_in[2];
    const int*   seg_i   = (const int*)  d_in[3];
    const float* centers = (const float*)d_in[4];
    const float* gammav  = (const float*)d_in[5];
    const float* W1      = (const float*)d_in[6];
    const float* b1      = (const float*)d_in[7];
    const float* W2      = (const float*)d_in[8];
    const float* b2      = (const float*)d_in[9];
    float* out = (float*)d_out;
    (void)in_sizes; (void)n_in;

    cudaFuncSetAttribute(cfconv_mma_kernel,
                         cudaFuncAttributeMaxDynamicSharedMemorySize, SMEM_BYTES);

    build_table_kernel<<<TABN + 1, DCH>>>(centers, gammav, W1, b1);
    build_w2_kernel<<<DCH, DCH>>>(W2);
    cudaMemsetAsync(d_out, 0, (size_t)out_size * sizeof(float), 0);
    cfconv_mma_kernel<<<GRID, TPB, SMEM_BYTES>>>(atom, dist, idx_j, seg_i, b2, out);
}

// round 9
// speedup vs baseline: 1.7653x; 1.7653x over previous
#include <cuda_runtime.h>
#include <cuda_fp16.h>
#include <cstdint>

// ---------------- problem constants ----------------
#define NB      2
#define NATOMS  25000
#define NE      400000
#define DCH     128
#define NRBF    64
#define CUTOFF  15.0f
#define TABN    8192

#define TILE_E       128
#define NTILES_PER_B (NE / TILE_E)       // 3125 exact
#define NTILES       (NB * NTILES_PER_B) // 6250
#define GRID         148
#define TPB          512                 // 16 warps

// distance -> h1 lookup table (f32): h1(d) = ssp(rbf(d)@W1 + b1)
__device__ float  g_table[(TABN + 1) * DCH];    // ~4.2 MB, L2-resident
// W2 packed for MMA-B: g_w2h[c*128 + k] = (half)W2[k][c]
__device__ __half g_w2h[DCH * DCH];             // 32 KB

// ---------------- smem layout (bytes) ----------------
#define BP      272                      // f16 tile row pitch (256B data + 16B pad)
#define FPITCH  130                      // F row pitch in floats (EVEN for float2)
#define TBYTES  (TILE_E * BP)            // 34816
#define SM_W2   0                        // 34816 : W2 [c][k] f16
#define SM_BT0  34816                    // 34816 : h1 tile buf 0
#define SM_BT1  69632                    // 34816 : h1 tile buf 1
#define SM_F    104448                   // 128*130*4 = 66560 : F [e][c] f32
#define SM_DIST 171008                   // 2*512
#define SM_IDX  172032                   // 2*512
#define SM_SEG  173056                   // 2*512
#define SMEM_BYTES 174080                // 170 KB

// ---------------- helpers ----------------
__device__ __forceinline__ uint32_t smem_u32(const void* p) {
    uint32_t a;
    asm("{ .reg .u64 t; cvta.to.shared.u64 t, %1; cvt.u32.u64 %0, t; }" : "=r"(a) : "l"(p));
    return a;
}
__device__ __forceinline__ uint32_t pack_half2(float x, float y) {  // lo=x, hi=y
    uint32_t u;
    asm("cvt.rn.f16x2.f32 %0, %1, %2;" : "=r"(u) : "f"(y), "f"(x));
    return u;
}
__device__ __forceinline__ void ldmat_x4(uint32_t& r0, uint32_t& r1, uint32_t& r2, uint32_t& r3,
                                         uint32_t addr) {
    asm volatile("ldmatrix.sync.aligned.m8n8.x4.shared.b16 {%0,%1,%2,%3}, [%4];"
                 : "=r"(r0), "=r"(r1), "=r"(r2), "=r"(r3) : "r"(addr));
}
__device__ __forceinline__ void mma16816(float* d, uint32_t a0, uint32_t a1, uint32_t a2, uint32_t a3,
                                         uint32_t b0, uint32_t b1) {
    asm volatile("mma.sync.aligned.m16n8k16.row.col.f32.f16.f16.f32 "
                 "{%0,%1,%2,%3}, {%4,%5,%6,%7}, {%8,%9}, {%0,%1,%2,%3};"
                 : "+f"(d[0]), "+f"(d[1]), "+f"(d[2]), "+f"(d[3])
                 : "r"(a0), "r"(a1), "r"(a2), "r"(a3), "r"(b0), "r"(b1));
}
__device__ __forceinline__ float ssp(float x) {
    float ax = fabsf(x);
    return fmaxf(x, 0.f) + __logf(1.f + __expf(-ax)) - 0.69314718056f;
}

// ---------------- prologue 1: h1(d) table (f32) ----------------
__global__ void build_table_kernel(const float* __restrict__ centers,
                                   const float* __restrict__ gammav,
                                   const float* __restrict__ W1,
                                   const float* __restrict__ b1) {
    __shared__ float rbf[NRBF];
    const int i = blockIdx.x;
    const int c = threadIdx.x;
    const float x = (float)i * (CUTOFF / (float)TABN);
    if (c < NRBF) {
        float t = x - centers[c];
        rbf[c] = __expf(-gammav[c] * t * t);
    }
    __syncthreads();
    float acc = b1[c];
    #pragma unroll
    for (int k = 0; k < NRBF; k++)
        acc = fmaf(rbf[k], W1[k * DCH + c], acc);
    g_table[i * DCH + c] = ssp(acc);
}

// ---------------- prologue 2: W2 -> f16 [c][k] ----------------
__global__ void build_w2_kernel(const float* __restrict__ W2) {
    const int c = blockIdx.x;
    const int k = threadIdx.x;
    g_w2h[c * DCH + k] = __float2half(W2[k * DCH + c]);
}

// ---------------- main fused kernel ----------------
__global__ __launch_bounds__(TPB, 1)
void cfconv_mma_kernel(const float* __restrict__ atom,   // [B, N, D]
                       const float* __restrict__ dist,   // [B, E]
                       const int*   __restrict__ idx_j,  // [E]
                       const int*   __restrict__ seg_i,  // [E] sorted
                       const float* __restrict__ b2,     // [D]
                       float*       __restrict__ out)    // [B, N, D] zeroed
{
    extern __shared__ char smem[];
    const uint32_t sb   = smem_u32(smem);
    const int tid  = threadIdx.x;
    const int wid  = tid >> 5;
    const int lane = tid & 31;

    // ---- load W2 f16 tile into padded smem (one-time) ----
    for (int i = tid; i < DCH * 16; i += TPB) {
        const int c = i >> 4, j = i & 15;
        *(uint4*)(smem + SM_W2 + c * BP + j * 16) =
            *(const uint4*)((const char*)g_w2h + (c * DCH + j * 8) * 2);
    }

    float* dist_s = (float*)(smem + SM_DIST);   // [2][128]
    int*   idx_s  = (int*)(smem + SM_IDX);      // [2][128]
    int*   seg_s  = (int*)(smem + SM_SEG);      // [2][128]
    float* Fs     = (float*)(smem + SM_F);

    // MMA mapping: 16 warps = 8 edge groups x 2 channel halves
    const int eq = wid & 7;       // edge group: rows eq*16 .. +15
    const int nh = wid >> 3;      // channel half: cols nh*64 .. +63
    const uint32_t a_row   = (uint32_t)(eq * 16 + (lane & 7) + ((lane >> 3) & 1) * 8);
    const uint32_t a_off   = a_row * BP + ((lane >> 4) & 1) * 16;   // + buffer base
    const uint32_t b_row   = (uint32_t)(nh * 64 + (lane & 7) + ((lane >> 4) & 1) * 8);
    const uint32_t b_addr0 = sb + SM_W2 + b_row * BP + ((lane >> 3) & 1) * 16;

    // epilogue mapping: 16 warps = 4 channel subs x 4 edge quarters
    const int   ec   = 32 * (wid & 3) + lane;   // channel
    const int   q    = wid >> 2;                // edge quarter (32 edges)
    const float b2c  = b2[ec];
    const float inv_h = (float)TABN / CUTOFF;

    // ---- prologue: stage + build tile 0 into buf 0 ----
    int T = blockIdx.x;
    if (tid < TILE_E) {
        const int b0i = T / NTILES_PER_B;
        const long e0 = (long)(T % NTILES_PER_B) * TILE_E;
        dist_s[tid] = dist[(size_t)b0i * NE + e0 + tid];
        idx_s[tid]  = idx_j[e0 + tid];
        seg_s[tid]  = seg_i[e0 + tid];
    }
    __syncthreads();
    // warp-cooperative build: warp w handles edges w*8..w*8+7, one row per LDG.128
    {
        char* bt = smem + SM_BT0;
        #pragma unroll
        for (int i = 0; i < 8; i++) {
            const int e = wid * 8 + i;
            float x = dist_s[e] * inv_h;
            int   ix = (int)x;
            ix = ix < 0 ? 0 : (ix > TABN - 1 ? TABN - 1 : ix);
            const float f = x - (float)ix;
            const float4 lo = *(const float4*)(g_table + (size_t)ix * DCH + lane * 4);
            const float4 hi = *(const float4*)(g_table + (size_t)(ix + 1) * DCH + lane * 4);
            uint2 u;
            u.x = pack_half2(fmaf(f, hi.x - lo.x, lo.x), fmaf(f, hi.y - lo.y, lo.y));
            u.y = pack_half2(fmaf(f, hi.z - lo.z, lo.z), fmaf(f, hi.w - lo.w, lo.w));
            *(uint2*)(bt + e * BP + lane * 8) = u;
        }
    }

    int it = 0;
    for (; T < NTILES; T += GRID, it++) {
        const int cur = it & 1;
        const int nxt = cur ^ 1;
        const int b   = T / NTILES_PER_B;
        const int Tn  = T + GRID;

        __syncthreads();   // BT[cur] built; Fs free (epilogue T-1 done); stage[nxt] slot free

        // ---- GEMM on BT[cur]: F[e][c] = sum_k h1[e][k] * W2[k][c] ----
        {
            const uint32_t a_addr = sb + (cur ? SM_BT1 : SM_BT0) + a_off;
            float acc[8][4];
            #pragma unroll
            for (int t = 0; t < 8; t++)
                acc[t][0] = acc[t][1] = acc[t][2] = acc[t][3] = 0.f;

            #pragma unroll
            for (int s = 0; s < 8; s++) {                  // K = 8 steps of 16
                uint32_t a0, a1, a2, a3;
                ldmat_x4(a0, a1, a2, a3, a_addr + s * 32);
                #pragma unroll
                for (int t2 = 0; t2 < 4; t2++) {           // 4 B ldmatrix -> 8 n-tiles
                    uint32_t b0, b1, b2r, b3;
                    ldmat_x4(b0, b1, b2r, b3, b_addr0 + t2 * 16 * BP + s * 32);
                    mma16816(acc[2 * t2],     a0, a1, a2, a3, b0,  b1);
                    mma16816(acc[2 * t2 + 1], a0, a1, a2, a3, b2r, b3);
                }
            }
            // store fragments -> F[e][c]
            const int er = eq * 16 + lane / 4;
            const int cc = nh * 64 + 2 * (lane & 3);
            #pragma unroll
            for (int t = 0; t < 8; t++) {
                const int cn = cc + 8 * t;
                *(float2*)(Fs + er * FPITCH + cn)       = make_float2(acc[t][0], acc[t][1]);
                *(float2*)(Fs + (er + 8) * FPITCH + cn) = make_float2(acc[t][2], acc[t][3]);
            }
        }

        // ---- stage scalars for next tile ----
        if (Tn < NTILES && tid < TILE_E) {
            const int bn  = Tn / NTILES_PER_B;
            const long en = (long)(Tn % NTILES_PER_B) * TILE_E;
            dist_s[nxt * TILE_E + tid] = dist[(size_t)bn * NE + en + tid];
            idx_s[nxt * TILE_E + tid]  = idx_j[en + tid];
            seg_s[nxt * TILE_E + tid]  = seg_i[en + tid];
        }
        __syncthreads();   // Fs + staged scalars visible

        // ---- build BT[nxt] (memory-heavy; its latency hides under epilogue) ----
        if (Tn < NTILES) {
            char* bt = smem + (nxt ? SM_BT1 : SM_BT0);
            const float* dsn = dist_s + nxt * TILE_E;
            #pragma unroll
            for (int i = 0; i < 8; i++) {
                const int e = wid * 8 + i;
                float x = dsn[e] * inv_h;
                int   ix = (int)x;
                ix = ix < 0 ? 0 : (ix > TABN - 1 ? TABN - 1 : ix);
                const float f = x - (float)ix;
                const float4 lo = *(const float4*)(g_table + (size_t)ix * DCH + lane * 4);
                const float4 hi = *(const float4*)(g_table + (size_t)(ix + 1) * DCH + lane * 4);
                uint2 u;
                u.x = pack_half2(fmaf(f, hi.x - lo.x, lo.x), fmaf(f, hi.y - lo.y, lo.y));
                u.y = pack_half2(fmaf(f, hi.z - lo.z, lo.z), fmaf(f, hi.w - lo.w, lo.w));
                *(uint2*)(bt + e * BP + lane * 8) = u;
            }
        }

        // ---- epilogue: +b2, ssp, gather, multiply, run-length scatter ----
        {
            const float* atomb = atom + (size_t)b * NATOMS * DCH;
            float*       outb  = out  + (size_t)b * NATOMS * DCH;
            const int*   isc   = idx_s + cur * TILE_E;
            const int*   ssc   = seg_s + cur * TILE_E;
            int   cseg = -1;
            float acc  = 0.f;
            const int eb = q * 32;
            #pragma unroll 4
            for (int j = 0; j < 32; j++) {
                const int   el   = eb + j;
                const float filt = ssp(Fs[el * FPITCH + ec] + b2c);
                const int   aj   = isc[el];
                const int   sg   = ssc[el];
                const float msg  = atomb[(size_t)aj * DCH + ec] * filt;
                if (sg != cseg) {
                    if (cseg >= 0) atomicAdd(outb + (size_t)cseg * DCH + ec, acc);
                    cseg = sg;
                    acc = msg;
                } else {
                    acc += msg;
                }
            }
            if (cseg >= 0) atomicAdd(outb + (size_t)cseg * DCH + ec, acc);
        }
    }
}

// ---------------- launch ----------------
extern "C" void kernel_launch(void* const* d_in, const int* in_sizes, int n_in,
                              void* d_out, int out_size) {
    const float* atom    = (const float*)d_in[0];
    const float* dist    = (const float*)d_in[1];
    const int*   idx_j   = (const int*)  d_in[2];
    const int*   seg_i   = (const int*)  d_in[3];
    const float* centers = (const float*)d_in[4];
    const float* gammav  = (const float*)d_in[5];
    const float* W1      = (const float*)d_in[6];
    const float* b1      = (const float*)d_in[7];
    const float* W2      = (const float*)d_in[8];
    const float* b2      = (const float*)d_in[9];
    float* out = (float*)d_out;
    (void)in_sizes; (void)n_in;

    cudaFuncSetAttribute(cfconv_mma_kernel,
                         cudaFuncAttributeMaxDynamicSharedMemorySize, SMEM_BYTES);

    build_table_kernel<<<TABN + 1, DCH>>>(centers, gammav, W1, b1);
    build_w2_kernel<<<DCH, DCH>>>(W2);
    cudaMemsetAsync(d_out, 0, (size_t)out_size * sizeof(float), 0);
    cfconv_mma_kernel<<<GRID, TPB, SMEM_BYTES>>>(atom, dist, idx_j, seg_i, b2, out);
}

// round 10
// speedup vs baseline: 2.6689x; 1.5119x over previous
#include <cuda_runtime.h>
#include <cuda_fp16.h>
#include <cstdint>

// ---------------- problem constants ----------------
#define NB      2
#define NATOMS  25000
#define NE      400000
#define DCH     128
#define NRBF    64
#define CUTOFF  15.0f
#define TABN    8192

#define TILE_E       128
#define NTILES_PER_B (NE / TILE_E)       // 3125 exact
#define NTILES       (NB * NTILES_PER_B) // 6250
#define GRID         148
#define TPB          512                 // 16 warps

// distance -> h1 lookup table (f32): h1(d) = ssp(rbf(d)@W1 + b1)
__device__ float  g_table[(TABN + 1) * DCH];    // ~4.2 MB, L2-resident
// W2 packed for MMA-B: g_w2h[c*128 + k] = (half)W2[k][c]
__device__ __half g_w2h[DCH * DCH];             // 32 KB

// ---------------- smem layout (bytes) ----------------
#define BP      272                      // f16 tile row pitch (256B data + 16B pad)
#define FPITCH  130                      // F row pitch in floats (EVEN for float2)
#define SM_W2   0                        // 34816 : W2 [c][k] f16
#define SM_BT0  34816                    // 34816 : h1 tile buf 0
#define SM_BT1  69632                    // 34816 : h1 tile buf 1
#define SM_F    104448                   // 128*130*4 = 66560 : F [e][c] f32
#define SM_DIST 171008                   // 2*512
#define SM_IDX  172032                   // 2*512
#define SM_SEG  173056                   // 2*512
#define SMEM_BYTES 174080                // 170 KB

// ---------------- helpers ----------------
__device__ __forceinline__ uint32_t smem_u32(const void* p) {
    uint32_t a;
    asm("{ .reg .u64 t; cvta.to.shared.u64 t, %1; cvt.u32.u64 %0, t; }" : "=r"(a) : "l"(p));
    return a;
}
__device__ __forceinline__ uint32_t pack_half2(float x, float y) {  // lo=x, hi=y
    uint32_t u;
    asm("cvt.rn.f16x2.f32 %0, %1, %2;" : "=r"(u) : "f"(y), "f"(x));
    return u;
}
__device__ __forceinline__ void ldmat_x4(uint32_t& r0, uint32_t& r1, uint32_t& r2, uint32_t& r3,
                                         uint32_t addr) {
    asm volatile("ldmatrix.sync.aligned.m8n8.x4.shared.b16 {%0,%1,%2,%3}, [%4];"
                 : "=r"(r0), "=r"(r1), "=r"(r2), "=r"(r3) : "r"(addr));
}
__device__ __forceinline__ void mma16816(float* d, uint32_t a0, uint32_t a1, uint32_t a2, uint32_t a3,
                                         uint32_t b0, uint32_t b1) {
    asm volatile("mma.sync.aligned.m16n8k16.row.col.f32.f16.f16.f32 "
                 "{%0,%1,%2,%3}, {%4,%5,%6,%7}, {%8,%9}, {%0,%1,%2,%3};"
                 : "+f"(d[0]), "+f"(d[1]), "+f"(d[2]), "+f"(d[3])
                 : "r"(a0), "r"(a1), "r"(a2), "r"(a3), "r"(b0), "r"(b1));
}
__device__ __forceinline__ float ssp(float x) {
    float ax = fabsf(x);
    return fmaxf(x, 0.f) + __logf(1.f + __expf(-ax)) - 0.69314718056f;
}

// ---------------- merged prologue: h1 table + W2 f16 pack (ONE launch) ----------------
__global__ void build_prologue_kernel(const float* __restrict__ centers,
                                      const float* __restrict__ gammav,
                                      const float* __restrict__ W1,
                                      const float* __restrict__ b1,
                                      const float* __restrict__ W2) {
    if (blockIdx.x <= TABN) {
        __shared__ float rbf[NRBF];
        const int i = blockIdx.x;
        const int c = threadIdx.x;
        const float x = (float)i * (CUTOFF / (float)TABN);
        if (c < NRBF) {
            float t = x - centers[c];
            rbf[c] = __expf(-gammav[c] * t * t);
        }
        __syncthreads();
        float acc = b1[c];
        #pragma unroll
        for (int k = 0; k < NRBF; k++)
            acc = fmaf(rbf[k], W1[k * DCH + c], acc);
        g_table[i * DCH + c] = ssp(acc);
    } else {
        // W2 pack: g_w2h[c*128 + k] = (half)W2[k][c]
        const int c = threadIdx.x;
        #pragma unroll 4
        for (int k = 0; k < DCH; k++)
            g_w2h[c * DCH + k] = __float2half(W2[k * DCH + c]);
    }
}

// ---------------- main fused kernel ----------------
__global__ __launch_bounds__(TPB, 1)
void cfconv_mma_kernel(const float* __restrict__ atom,   // [B, N, D]
                       const float* __restrict__ dist,   // [B, E]
                       const int*   __restrict__ idx_j,  // [E]
                       const int*   __restrict__ seg_i,  // [E] sorted
                       const float* __restrict__ b2,     // [D]
                       float*       __restrict__ out)    // [B, N, D] zeroed
{
    extern __shared__ char smem[];
    const uint32_t sb   = smem_u32(smem);
    const int tid  = threadIdx.x;
    const int wid  = tid >> 5;
    const int lane = tid & 31;

    // ---- load W2 f16 tile into padded smem (one-time) ----
    for (int i = tid; i < DCH * 16; i += TPB) {
        const int c = i >> 4, j = i & 15;
        *(uint4*)(smem + SM_W2 + c * BP + j * 16) =
            *(const uint4*)((const char*)g_w2h + (c * DCH + j * 8) * 2);
    }

    float* dist_s = (float*)(smem + SM_DIST);   // [2][128]
    int*   idx_s  = (int*)(smem + SM_IDX);      // [2][128]
    int*   seg_s  = (int*)(smem + SM_SEG);      // [2][128]
    float* Fs     = (float*)(smem + SM_F);

    // MMA mapping: 16 warps = 8 edge groups x 2 channel halves
    const int eq = wid & 7;
    const int nh = wid >> 3;
    const uint32_t a_row   = (uint32_t)(eq * 16 + (lane & 7) + ((lane >> 3) & 1) * 8);
    const uint32_t a_off   = a_row * BP + ((lane >> 4) & 1) * 16;
    const uint32_t b_row   = (uint32_t)(nh * 64 + (lane & 7) + ((lane >> 4) & 1) * 8);
    const uint32_t b_addr0 = sb + SM_W2 + b_row * BP + ((lane >> 3) & 1) * 16;

    // epilogue mapping: 16 warps = 4 channel subs x 4 edge quarters
    const int   ec   = 32 * (wid & 3) + lane;
    const int   q    = wid >> 2;
    const float b2c  = b2[ec];
    const float inv_h = (float)TABN / CUTOFF;

    // ---- prologue: stage + build tile 0 into buf 0 ----
    int T = blockIdx.x;
    if (tid < TILE_E) {
        const int b0i = T / NTILES_PER_B;
        const long e0 = (long)(T % NTILES_PER_B) * TILE_E;
        dist_s[tid] = dist[(size_t)b0i * NE + e0 + tid];
        idx_s[tid]  = idx_j[e0 + tid];
        seg_s[tid]  = seg_i[e0 + tid];
    }
    __syncthreads();
    {
        char* bt = smem + SM_BT0;
        #pragma unroll
        for (int i = 0; i < 8; i++) {
            const int e = wid * 8 + i;
            float x = dist_s[e] * inv_h;
            int   ix = (int)x;
            ix = ix < 0 ? 0 : (ix > TABN - 1 ? TABN - 1 : ix);
            const float f = x - (float)ix;
            const float4 lo = *(const float4*)(g_table + (size_t)ix * DCH + lane * 4);
            const float4 hi = *(const float4*)(g_table + (size_t)(ix + 1) * DCH + lane * 4);
            uint2 u;
            u.x = pack_half2(fmaf(f, hi.x - lo.x, lo.x), fmaf(f, hi.y - lo.y, lo.y));
            u.y = pack_half2(fmaf(f, hi.z - lo.z, lo.z), fmaf(f, hi.w - lo.w, lo.w));
            *(uint2*)(bt + e * BP + lane * 8) = u;
        }
    }

    int it = 0;
    for (; T < NTILES; T += GRID, it++) {
        const int cur = it & 1;
        const int nxt = cur ^ 1;
        const int b   = T / NTILES_PER_B;
        const int Tn  = T + GRID;

        __syncthreads();   // BT[cur] built; Fs + stage[nxt] free (epilogue T-1 done)

        // ---- stage scalars for next tile (overlaps GEMM below) ----
        if (Tn < NTILES && tid < TILE_E) {
            const int bn  = Tn / NTILES_PER_B;
            const long en = (long)(Tn % NTILES_PER_B) * TILE_E;
            dist_s[nxt * TILE_E + tid] = dist[(size_t)bn * NE + en + tid];
            idx_s[nxt * TILE_E + tid]  = idx_j[en + tid];
            seg_s[nxt * TILE_E + tid]  = seg_i[en + tid];
        }

        // ---- GEMM on BT[cur]: F[e][c] = sum_k h1[e][k] * W2[k][c] ----
        {
            const uint32_t a_addr = sb + (cur ? SM_BT1 : SM_BT0) + a_off;
            float acc[8][4];
            #pragma unroll
            for (int t = 0; t < 8; t++)
                acc[t][0] = acc[t][1] = acc[t][2] = acc[t][3] = 0.f;

            #pragma unroll
            for (int s = 0; s < 8; s++) {
                uint32_t a0, a1, a2, a3;
                ldmat_x4(a0, a1, a2, a3, a_addr + s * 32);
                #pragma unroll
                for (int t2 = 0; t2 < 4; t2++) {
                    uint32_t b0, b1, b2r, b3;
                    ldmat_x4(b0, b1, b2r, b3, b_addr0 + t2 * 16 * BP + s * 32);
                    mma16816(acc[2 * t2],     a0, a1, a2, a3, b0,  b1);
                    mma16816(acc[2 * t2 + 1], a0, a1, a2, a3, b2r, b3);
                }
            }
            const int er = eq * 16 + lane / 4;
            const int cc = nh * 64 + 2 * (lane & 3);
            #pragma unroll
            for (int t = 0; t < 8; t++) {
                const int cn = cc + 8 * t;
                *(float2*)(Fs + er * FPITCH + cn)       = make_float2(acc[t][0], acc[t][1]);
                *(float2*)(Fs + (er + 8) * FPITCH + cn) = make_float2(acc[t][2], acc[t][3]);
            }
        }
        __syncthreads();   // Fs complete + staged scalars visible

        // ---- build BT[nxt] (L2-heavy; overlaps epilogue below) ----
        if (Tn < NTILES) {
            char* bt = smem + (nxt ? SM_BT1 : SM_BT0);
            const float* dsn = dist_s + nxt * TILE_E;
            #pragma unroll
            for (int i = 0; i < 8; i++) {
                const int e = wid * 8 + i;
                float x = dsn[e] * inv_h;
                int   ix = (int)x;
                ix = ix < 0 ? 0 : (ix > TABN - 1 ? TABN - 1 : ix);
                const float f = x - (float)ix;
                const float4 lo = *(const float4*)(g_table + (size_t)ix * DCH + lane * 4);
                const float4 hi = *(const float4*)(g_table + (size_t)(ix + 1) * DCH + lane * 4);
                uint2 u;
                u.x = pack_half2(fmaf(f, hi.x - lo.x, lo.x), fmaf(f, hi.y - lo.y, lo.y));
                u.y = pack_half2(fmaf(f, hi.z - lo.z, lo.z), fmaf(f, hi.w - lo.w, lo.w));
                *(uint2*)(bt + e * BP + lane * 8) = u;
            }
        }

        // ---- epilogue: branch-free gather/ssp chunks + run-length scatter ----
        {
            const float* atomb = atom + (size_t)b * NATOMS * DCH;
            float*       outb  = out  + (size_t)b * NATOMS * DCH;
            const int*   isc   = idx_s + cur * TILE_E;
            const int*   ssc   = seg_s + cur * TILE_E;
            const int eb = q * 32;

            float gv[2][8];
            #pragma unroll
            for (int j = 0; j < 8; j++)
                gv[0][j] = atomb[(size_t)isc[eb + j] * DCH + ec];

            int   cseg = -1;
            float acc  = 0.f;
            #pragma unroll
            for (int ck = 0; ck < 4; ck++) {
                const int cb = ck & 1, nb = cb ^ 1;
                if (ck < 3) {
                    #pragma unroll
                    for (int j = 0; j < 8; j++)
                        gv[nb][j] = atomb[(size_t)isc[eb + (ck + 1) * 8 + j] * DCH + ec];
                }
                float msg[8];
                #pragma unroll
                for (int j = 0; j < 8; j++)
                    msg[j] = gv[cb][j] * ssp(Fs[(eb + ck * 8 + j) * FPITCH + ec] + b2c);
                #pragma unroll
                for (int j = 0; j < 8; j++) {
                    const int sg = ssc[eb + ck * 8 + j];
                    if (sg != cseg) {
                        if (cseg >= 0) atomicAdd(outb + (size_t)cseg * DCH + ec, acc);
                        cseg = sg;
                        acc = msg[j];
                    } else {
                        acc += msg[j];
                    }
                }
            }
            if (cseg >= 0) atomicAdd(outb + (size_t)cseg * DCH + ec, acc);
        }
    }
}

// ---------------- launch ----------------
extern "C" void kernel_launch(void* const* d_in, const int* in_sizes, int n_in,
                              void* d_out, int out_size) {
    const float* atom    = (const float*)d_in[0];
    const float* dist    = (const float*)d_in[1];
    const int*   idx_j   = (const int*)  d_in[2];
    const int*   seg_i   = (const int*)  d_in[3];
    const float* centers = (const float*)d_in[4];
    const float* gammav  = (const float*)d_in[5];
    const float* W1      = (const float*)d_in[6];
    const float* b1      = (const float*)d_in[7];
    const float* W2      = (const float*)d_in[8];
    const float* b2      = (const float*)d_in[9];
    float* out = (float*)d_out;
    (void)in_sizes; (void)n_in;

    cudaFuncSetAttribute(cfconv_mma_kernel,
                         cudaFuncAttributeMaxDynamicSharedMemorySize, SMEM_BYTES);

    build_prologue_kernel<<<TABN + 2, DCH>>>(centers, gammav, W1, b1, W2);
    cudaMemsetAsync(d_out, 0, (size_t)out_size * sizeof(float), 0);
    cfconv_mma_kernel<<<GRID, TPB, SMEM_BYTES>>>(atom, dist, idx_j, seg_i, b2, out);
}

// round 12
// speedup vs baseline: 3.0234x; 1.1328x over previous
#include <cuda_runtime.h>
#include <cuda_fp16.h>
#include <cstdint>

// ---------------- problem constants ----------------
#define NB      2
#define NATOMS  25000
#define NE      400000
#define DCH     128
#define NRBF    64
#define CUTOFF  15.0f
#define TABN    8192

#define TILE_E       64
#define NTILES_PER_B (NE / TILE_E)       // 6250 exact
#define NTILES       (NB * NTILES_PER_B) // 12500
#define GRID         296                 // 2 blocks/SM
#define TPB          512                 // 16 warps

// distance -> h1 lookup table (f32): h1(d) = ssp(rbf(d)@W1 + b1)
__device__ float  g_table[(TABN + 1) * DCH];    // ~4.2 MB, L2-resident
// W2 packed for MMA-B: g_w2h[c*128 + k] = (half)W2[k][c]
__device__ __half g_w2h[DCH * DCH];             // 32 KB

// ---------------- smem layout (bytes) ----------------
#define BP      272                      // f16 tile row pitch (256B data + 16B pad)
#define FPITCH  130                      // F row pitch in floats (EVEN for float2)
#define SM_W2   0                        // 128*272 = 34816 : W2 [c][k] f16
#define SM_BT0  34816                    // 64*272 = 17408 : h1 tile buf 0
#define SM_BT1  52224                    // 17408 : h1 tile buf 1
#define SM_F    69632                    // 64*130*4 = 33280 : F [e][c] f32
#define SM_DIST 102912                   // 2*256
#define SM_IDX  103424                   // 2*256
#define SM_SEG  103936                   // 2*256
#define SMEM_BYTES 104448                // 102 KB -> 2 blocks/SM

// ---------------- helpers ----------------
__device__ __forceinline__ uint32_t smem_u32(const void* p) {
    uint32_t a;
    asm("{ .reg .u64 t; cvta.to.shared.u64 t, %1; cvt.u32.u64 %0, t; }" : "=r"(a) : "l"(p));
    return a;
}
__device__ __forceinline__ uint32_t pack_half2(float x, float y) {  // lo=x, hi=y
    uint32_t u;
    asm("cvt.rn.f16x2.f32 %0, %1, %2;" : "=r"(u) : "f"(y), "f"(x));
    return u;
}
__device__ __forceinline__ void ldmat_x4(uint32_t& r0, uint32_t& r1, uint32_t& r2, uint32_t& r3,
                                         uint32_t addr) {
    asm volatile("ldmatrix.sync.aligned.m8n8.x4.shared.b16 {%0,%1,%2,%3}, [%4];"
                 : "=r"(r0), "=r"(r1), "=r"(r2), "=r"(r3) : "r"(addr));
}
__device__ __forceinline__ void mma16816(float* d, uint32_t a0, uint32_t a1, uint32_t a2, uint32_t a3,
                                         uint32_t b0, uint32_t b1) {
    asm volatile("mma.sync.aligned.m16n8k16.row.col.f32.f16.f16.f32 "
                 "{%0,%1,%2,%3}, {%4,%5,%6,%7}, {%8,%9}, {%0,%1,%2,%3};"
                 : "+f"(d[0]), "+f"(d[1]), "+f"(d[2]), "+f"(d[3])
                 : "r"(a0), "r"(a1), "r"(a2), "r"(a3), "r"(b0), "r"(b1));
}
__device__ __forceinline__ float ssp(float x) {
    float ax = fabsf(x);
    return fmaxf(x, 0.f) + __logf(1.f + __expf(-ax)) - 0.69314718056f;
}

// ---------------- merged prologue: h1 table + W2 f16 pack (ONE launch) ----------------
__global__ void build_prologue_kernel(const float* __restrict__ centers,
                                      const float* __restrict__ gammav,
                                      const float* __restrict__ W1,
                                      const float* __restrict__ b1,
                                      const float* __restrict__ W2) {
    if (blockIdx.x <= TABN) {
        __shared__ float rbf[NRBF];
        const int i = blockIdx.x;
        const int c = threadIdx.x;
        const float x = (float)i * (CUTOFF / (float)TABN);
        if (c < NRBF) {
            float t = x - centers[c];
            rbf[c] = __expf(-gammav[c] * t * t);
        }
        __syncthreads();
        float acc = b1[c];
        #pragma unroll
        for (int k = 0; k < NRBF; k++)
            acc = fmaf(rbf[k], W1[k * DCH + c], acc);
        g_table[i * DCH + c] = ssp(acc);
    } else {
        const int c = threadIdx.x;
        #pragma unroll 4
        for (int k = 0; k < DCH; k++)
            g_w2h[c * DCH + k] = __float2half(W2[k * DCH + c]);
    }
}

// ---------------- main fused kernel ----------------
__global__ __launch_bounds__(TPB, 2)
void cfconv_mma_kernel(const float* __restrict__ atom,   // [B, N, D]
                       const float* __restrict__ dist,   // [B, E]
                       const int*   __restrict__ idx_j,  // [E]
                       const int*   __restrict__ seg_i,  // [E] sorted
                       const float* __restrict__ b2,     // [D]
                       float*       __restrict__ out)    // [B, N, D] zeroed
{
    extern __shared__ char smem[];
    const uint32_t sb   = smem_u32(smem);
    const int tid  = threadIdx.x;
    const int wid  = tid >> 5;
    const int lane = tid & 31;

    // ---- load W2 f16 tile into padded smem (one-time) ----
    for (int i = tid; i < DCH * 16; i += TPB) {
        const int c = i >> 4, j = i & 15;
        *(uint4*)(smem + SM_W2 + c * BP + j * 16) =
            *(const uint4*)((const char*)g_w2h + (c * DCH + j * 8) * 2);
    }

    float* dist_s = (float*)(smem + SM_DIST);   // [2][64]
    int*   idx_s  = (int*)(smem + SM_IDX);      // [2][64]
    int*   seg_s  = (int*)(smem + SM_SEG);      // [2][64]
    float* Fs     = (float*)(smem + SM_F);

    // MMA mapping: 16 warps = 4 edge groups (16 rows) x 4 channel quarters (32 ch)
    const int eq = wid & 3;
    const int nq = wid >> 2;
    const uint32_t a_row   = (uint32_t)(eq * 16 + (lane & 7) + ((lane >> 3) & 1) * 8);
    const uint32_t a_off   = a_row * BP + ((lane >> 4) & 1) * 16;
    const uint32_t b_row   = (uint32_t)(nq * 32 + (lane & 7) + ((lane >> 4) & 1) * 8);
    const uint32_t b_addr0 = sb + SM_W2 + b_row * BP + ((lane >> 3) & 1) * 16;

    // epilogue mapping: 16 warps = 4 channel subs x 4 edge quarters (16 edges)
    const int   ec   = 32 * (wid & 3) + lane;
    const int   q    = wid >> 2;
    const float b2c  = b2[ec];
    const float inv_h = (float)TABN / CUTOFF;

    // ---- prologue: stage + build tile 0 into buf 0 ----
    int T = blockIdx.x;
    if (tid < TILE_E) {
        const int b0i = T / NTILES_PER_B;
        const long e0 = (long)(T % NTILES_PER_B) * TILE_E;
        dist_s[tid] = dist[(size_t)b0i * NE + e0 + tid];
        idx_s[tid]  = idx_j[e0 + tid];
        seg_s[tid]  = seg_i[e0 + tid];
    }
    __syncthreads();
    {   // warp-cooperative build: warp w -> edges w*4..w*4+3, one row per LDG.128 pair
        char* bt = smem + SM_BT0;
        #pragma unroll
        for (int i = 0; i < 4; i++) {
            const int e = wid * 4 + i;
            float x = dist_s[e] * inv_h;
            int   ix = (int)x;
            ix = ix < 0 ? 0 : (ix > TABN - 1 ? TABN - 1 : ix);
            const float f = x - (float)ix;
            const float4 lo = *(const float4*)(g_table + (size_t)ix * DCH + lane * 4);
            const float4 hi = *(const float4*)(g_table + (size_t)(ix + 1) * DCH + lane * 4);
            uint2 u;
            u.x = pack_half2(fmaf(f, hi.x - lo.x, lo.x), fmaf(f, hi.y - lo.y, lo.y));
            u.y = pack_half2(fmaf(f, hi.z - lo.z, lo.z), fmaf(f, hi.w - lo.w, lo.w));
            *(uint2*)(bt + e * BP + lane * 8) = u;
        }
    }

    int it = 0;
    for (; T < NTILES; T += GRID, it++) {
        const int cur = it & 1;
        const int nxt = cur ^ 1;
        const int b   = T / NTILES_PER_B;
        const int Tn  = T + GRID;

        __syncthreads();   // BT[cur] built; Fs + stage[nxt] free

        // ---- stage scalars for next tile (overlaps GEMM) ----
        if (Tn < NTILES && tid < TILE_E) {
            const int bn  = Tn / NTILES_PER_B;
            const long en = (long)(Tn % NTILES_PER_B) * TILE_E;
            dist_s[nxt * TILE_E + tid] = dist[(size_t)bn * NE + en + tid];
            idx_s[nxt * TILE_E + tid]  = idx_j[en + tid];
            seg_s[nxt * TILE_E + tid]  = seg_i[en + tid];
        }

        // ---- GEMM on BT[cur]: F[e][c] = sum_k h1[e][k] * W2[k][c] ----
        {
            const uint32_t a_addr = sb + (cur ? SM_BT1 : SM_BT0) + a_off;
            float acc[4][4];
            #pragma unroll
            for (int t = 0; t < 4; t++)
                acc[t][0] = acc[t][1] = acc[t][2] = acc[t][3] = 0.f;

            #pragma unroll
            for (int s = 0; s < 8; s++) {                  // K = 8 steps of 16
                uint32_t a0, a1, a2, a3;
                ldmat_x4(a0, a1, a2, a3, a_addr + s * 32);
                #pragma unroll
                for (int t2 = 0; t2 < 2; t2++) {           // 2 B ldmatrix -> 4 n-tiles
                    uint32_t b0, b1, b2r, b3;
                    ldmat_x4(b0, b1, b2r, b3, b_addr0 + t2 * 16 * BP + s * 32);
                    mma16816(acc[2 * t2],     a0, a1, a2, a3, b0,  b1);
                    mma16816(acc[2 * t2 + 1], a0, a1, a2, a3, b2r, b3);
                }
            }
            const int er = eq * 16 + lane / 4;
            const int cc = nq * 32 + 2 * (lane & 3);
            #pragma unroll
            for (int t = 0; t < 4; t++) {
                const int cn = cc + 8 * t;
                *(float2*)(Fs + er * FPITCH + cn)       = make_float2(acc[t][0], acc[t][1]);
                *(float2*)(Fs + (er + 8) * FPITCH + cn) = make_float2(acc[t][2], acc[t][3]);
            }
        }
        __syncthreads();   // Fs complete + staged scalars visible

        // ---- build BT[nxt] (L2-heavy; overlaps epilogue) ----
        if (Tn < NTILES) {
            char* bt = smem + (nxt ? SM_BT1 : SM_BT0);
            const float* dsn = dist_s + nxt * TILE_E;
            #pragma unroll
            for (int i = 0; i < 4; i++) {
                const int e = wid * 4 + i;
                float x = dsn[e] * inv_h;
                int   ix = (int)x;
                ix = ix < 0 ? 0 : (ix > TABN - 1 ? TABN - 1 : ix);
                const float f = x - (float)ix;
                const float4 lo = *(const float4*)(g_table + (size_t)ix * DCH + lane * 4);
                const float4 hi = *(const float4*)(g_table + (size_t)(ix + 1) * DCH + lane * 4);
                uint2 u;
                u.x = pack_half2(fmaf(f, hi.x - lo.x, lo.x), fmaf(f, hi.y - lo.y, lo.y));
                u.y = pack_half2(fmaf(f, hi.z - lo.z, lo.z), fmaf(f, hi.w - lo.w, lo.w));
                *(uint2*)(bt + e * BP + lane * 8) = u;
            }
        }

        // ---- epilogue: branch-free gather/ssp chunks + run-length scatter ----
        {
            const float* atomb = atom + (size_t)b * NATOMS * DCH;
            float*       outb  = out  + (size_t)b * NATOMS * DCH;
            const int*   isc   = idx_s + cur * TILE_E;
            const int*   ssc   = seg_s + cur * TILE_E;
            const int eb = q * 16;

            float gv[2][8];
            #pragma unroll
            for (int j = 0; j < 8; j++)
                gv[0][j] = atomb[(size_t)isc[eb + j] * DCH + ec];

            int   cseg = -1;
            float acc  = 0.f;
            #pragma unroll
            for (int ck = 0; ck < 2; ck++) {
                const int cb = ck & 1, nb = cb ^ 1;
                if (ck < 1) {
                    #pragma unroll
                    for (int j = 0; j < 8; j++)
                        gv[nb][j] = atomb[(size_t)isc[eb + 8 + j] * DCH + ec];
                }
                float msg[8];
                #pragma unroll
                for (int j = 0; j < 8; j++)
                    msg[j] = gv[cb][j] * ssp(Fs[(eb + ck * 8 + j) * FPITCH + ec] + b2c);
                #pragma unroll
                for (int j = 0; j < 8; j++) {
                    const int sg = ssc[eb + ck * 8 + j];
                    if (sg != cseg) {
                        if (cseg >= 0) atomicAdd(outb + (size_t)cseg * DCH + ec, acc);
                        cseg = sg;
                        acc = msg[j];
                    } else {
                        acc += msg[j];
                    }
                }
            }
            if (cseg >= 0) atomicAdd(outb + (size_t)cseg * DCH + ec, acc);
        }
    }
}

// ---------------- launch ----------------
extern "C" void kernel_launch(void* const* d_in, const int* in_sizes, int n_in,
                              void* d_out, int out_size) {
    const float* atom    = (const float*)d_in[0];
    const float* dist    = (const float*)d_in[1];
    const int*   idx_j   = (const int*)  d_in[2];
    const int*   seg_i   = (const int*)  d_in[3];
    const float* centers = (const float*)d_in[4];
    const float* gammav  = (const float*)d_in[5];
    const float* W1      = (const float*)d_in[6];
    const float* b1      = (const float*)d_in[7];
    const float* W2      = (const float*)d_in[8];
    const float* b2      = (const float*)d_in[9];
    float* out = (float*)d_out;
    (void)in_sizes; (void)n_in;

    cudaFuncSetAttribute(cfconv_mma_kernel,
                         cudaFuncAttributeMaxDynamicSharedMemorySize, SMEM_BYTES);

    build_prologue_kernel<<<TABN + 2, DCH>>>(centers, gammav, W1, b1, W2);
    cudaMemsetAsync(d_out, 0, (size_t)out_size * sizeof(float), 0);
    cfconv_mma_kernel<<<GRID, TPB, SMEM_BYTES>>>(atom, dist, idx_j, seg_i, b2, out);
}

// round 13
// speedup vs baseline: 3.2593x; 1.0780x over previous
#include <cuda_runtime.h>
#include <cuda_fp16.h>
#include <cstdint>

// ---------------- problem constants ----------------
#define NB      2
#define NATOMS  25000
#define NE      400000
#define DCH     128
#define NRBF    64
#define CUTOFF  15.0f
#define TABN    8192

#define TILE_E       32
#define NTILES_PER_B (NE / TILE_E)       // 12500 exact
#define NTILES       (NB * NTILES_PER_B) // 25000
#define GRID         296                 // 2 blocks/SM
#define TPB          512                 // 16 warps = 2 groups of 8
#define NSTREAM      (GRID * 2)          // 592 tile streams

// distance -> h1 lookup table in f16 (h1 rounds to f16 for MMA anyway)
__device__ __half g_tab16[(TABN + 1) * DCH];    // ~2.1 MB, L2-resident
// W2 packed for MMA-B: g_w2h[c*128 + k] = (half)W2[k][c]
__device__ __half g_w2h[DCH * DCH];             // 32 KB

// ---------------- smem layout (bytes) ----------------
#define BP      272                      // f16 tile row pitch (256B data + 16B pad)
#define FPITCH  130                      // F row pitch in floats (EVEN for float2)
#define SM_W2   0                        // 128*272 = 34816 : W2 [c][k] f16 (shared by both groups)
// per-group region: base = 34816 + g*34816
//   BT0  : +0      (32*272 = 8704)
//   BT1  : +8704   (8704)
//   Fs   : +17408  (32*130*4 = 16640)
//   dist : +34048  (2*32*4 = 256)
//   idx  : +34304  (256)
//   seg  : +34560  (256)   -> total 34816
#define GRP_BT0   0
#define GRP_BT1   8704
#define GRP_F     17408
#define GRP_DIST  34048
#define GRP_IDX   34304
#define GRP_SEG   34560
#define GRP_SIZE  34816
#define SMEM_BYTES (34816 * 3)           // 104448 -> 2 blocks/SM

// ---------------- helpers ----------------
__device__ __forceinline__ uint32_t smem_u32(const void* p) {
    uint32_t a;
    asm("{ .reg .u64 t; cvta.to.shared.u64 t, %1; cvt.u32.u64 %0, t; }" : "=r"(a) : "l"(p));
    return a;
}
__device__ __forceinline__ uint32_t pack_half2(float x, float y) {  // lo=x, hi=y
    uint32_t u;
    asm("cvt.rn.f16x2.f32 %0, %1, %2;" : "=r"(u) : "f"(y), "f"(x));
    return u;
}
__device__ __forceinline__ void bar_grp(int id) {   // 256-thread named barrier
    asm volatile("bar.sync %0, 256;" :: "r"(id) : "memory");
}
__device__ __forceinline__ void ldmat_x4(uint32_t& r0, uint32_t& r1, uint32_t& r2, uint32_t& r3,
                                         uint32_t addr) {
    asm volatile("ldmatrix.sync.aligned.m8n8.x4.shared.b16 {%0,%1,%2,%3}, [%4];"
                 : "=r"(r0), "=r"(r1), "=r"(r2), "=r"(r3) : "r"(addr));
}
__device__ __forceinline__ void mma16816(float* d, uint32_t a0, uint32_t a1, uint32_t a2, uint32_t a3,
                                         uint32_t b0, uint32_t b1) {
    asm volatile("mma.sync.aligned.m16n8k16.row.col.f32.f16.f16.f32 "
                 "{%0,%1,%2,%3}, {%4,%5,%6,%7}, {%8,%9}, {%0,%1,%2,%3};"
                 : "+f"(d[0]), "+f"(d[1]), "+f"(d[2]), "+f"(d[3])
                 : "r"(a0), "r"(a1), "r"(a2), "r"(a3), "r"(b0), "r"(b1));
}
__device__ __forceinline__ float ssp(float x) {
    float ax = fabsf(x);
    return fmaxf(x, 0.f) + __logf(1.f + __expf(-ax)) - 0.69314718056f;
}

// ---------------- merged prologue: f16 h1 table + W2 f16 pack ----------------
__global__ void build_prologue_kernel(const float* __restrict__ centers,
                                      const float* __restrict__ gammav,
                                      const float* __restrict__ W1,
                                      const float* __restrict__ b1,
                                      const float* __restrict__ W2) {
    if (blockIdx.x <= TABN) {
        __shared__ float rbf[NRBF];
        const int i = blockIdx.x;
        const int c = threadIdx.x;
        const float x = (float)i * (CUTOFF / (float)TABN);
        if (c < NRBF) {
            float t = x - centers[c];
            rbf[c] = __expf(-gammav[c] * t * t);
        }
        __syncthreads();
        float acc = b1[c];
        #pragma unroll
        for (int k = 0; k < NRBF; k++)
            acc = fmaf(rbf[k], W1[k * DCH + c], acc);
        g_tab16[i * DCH + c] = __float2half(ssp(acc));
    } else {
        const int c = threadIdx.x;
        #pragma unroll 4
        for (int k = 0; k < DCH; k++)
            g_w2h[c * DCH + k] = __float2half(W2[k * DCH + c]);
    }
}

// ---------------- build one 32-edge h1 tile (per-group, warp-cooperative) ----------------
__device__ __forceinline__ void build_tile(char* bt, const float* ds,
                                           int gwid, int lane, float inv_h) {
    #pragma unroll
    for (int i = 0; i < 4; i++) {
        const int e = gwid * 4 + i;
        float x = ds[e] * inv_h;
        int   ix = (int)x;
        ix = ix < 0 ? 0 : (ix > TABN - 1 ? TABN - 1 : ix);
        const float f = x - (float)ix;
        const uint2 ulo = *(const uint2*)((const char*)g_tab16 + ((size_t)ix * DCH + lane * 4) * 2);
        const uint2 uhi = *(const uint2*)((const char*)g_tab16 + ((size_t)(ix + 1) * DCH + lane * 4) * 2);
        const float2 l0 = __half22float2(*(const __half2*)&ulo.x);
        const float2 l1 = __half22float2(*(const __half2*)&ulo.y);
        const float2 h0 = __half22float2(*(const __half2*)&uhi.x);
        const float2 h1 = __half22float2(*(const __half2*)&uhi.y);
        uint2 u;
        u.x = pack_half2(fmaf(f, h0.x - l0.x, l0.x), fmaf(f, h0.y - l0.y, l0.y));
        u.y = pack_half2(fmaf(f, h1.x - l1.x, l1.x), fmaf(f, h1.y - l1.y, l1.y));
        *(uint2*)(bt + e * BP + lane * 8) = u;
    }
}

// ---------------- main fused kernel ----------------
__global__ __launch_bounds__(TPB, 2)
void cfconv_mma_kernel(const float* __restrict__ atom,   // [B, N, D]
                       const float* __restrict__ dist,   // [B, E]
                       const int*   __restrict__ idx_j,  // [E]
                       const int*   __restrict__ seg_i,  // [E] sorted
                       const float* __restrict__ b2,     // [D]
                       float*       __restrict__ out)    // [B, N, D] zeroed
{
    extern __shared__ char smem[];
    const uint32_t sb   = smem_u32(smem);
    const int tid   = threadIdx.x;
    const int wid   = tid >> 5;
    const int lane  = tid & 31;
    const int g     = wid >> 3;          // group 0/1
    const int gwid  = wid & 7;           // warp id within group
    const int tid_g = tid & 255;
    const int bar_id = 1 + g;

    // ---- load W2 f16 tile into padded smem (one-time, whole block) ----
    for (int i = tid; i < DCH * 16; i += TPB) {
        const int c = i >> 4, j = i & 15;
        *(uint4*)(smem + SM_W2 + c * BP + j * 16) =
            *(const uint4*)((const char*)g_w2h + (c * DCH + j * 8) * 2);
    }

    char*  grp    = smem + 34816 + g * GRP_SIZE;
    float* dist_s = (float*)(grp + GRP_DIST);   // [2][32]
    int*   idx_s  = (int*)(grp + GRP_IDX);      // [2][32]
    int*   seg_s  = (int*)(grp + GRP_SEG);      // [2][32]
    float* Fs     = (float*)(grp + GRP_F);

    // MMA mapping: 8 warps = 2 edge groups (16 rows) x 4 channel quarters (32 ch)
    const int eq = gwid & 1;
    const int nq = gwid >> 1;
    const uint32_t a_row   = (uint32_t)(eq * 16 + (lane & 7) + ((lane >> 3) & 1) * 8);
    const uint32_t a_off   = a_row * BP + ((lane >> 4) & 1) * 16;
    const uint32_t b_row   = (uint32_t)(nq * 32 + (lane & 7) + ((lane >> 4) & 1) * 8);
    const uint32_t b_addr0 = sb + SM_W2 + b_row * BP + ((lane >> 3) & 1) * 16;

    // epilogue mapping: 8 warps = 4 channel subs x 2 edge halves (16 edges)
    const int   ec   = 32 * (gwid & 3) + lane;
    const int   q    = gwid >> 2;
    const float b2c  = b2[ec];
    const float inv_h = (float)TABN / CUTOFF;

    // ---- prologue: stage + build tile 0 into buf 0 ----
    const int sid = blockIdx.x * 2 + g;          // this group's stream
    int T = sid;
    if (T < NTILES && tid_g < TILE_E) {
        const int b0i = T / NTILES_PER_B;
        const long e0 = (long)(T % NTILES_PER_B) * TILE_E;
        dist_s[tid_g] = dist[(size_t)b0i * NE + e0 + tid_g];
        idx_s[tid_g]  = idx_j[e0 + tid_g];
        seg_s[tid_g]  = seg_i[e0 + tid_g];
    }
    __syncthreads();                              // W2 + stage visible (whole block, once)
    if (T < NTILES)
        build_tile(grp + GRP_BT0, dist_s, gwid, lane, inv_h);

    int it = 0;
    for (; T < NTILES; T += NSTREAM, it++) {
        const int cur = it & 1;
        const int nxt = cur ^ 1;
        const int b   = T / NTILES_PER_B;
        const int Tn  = T + NSTREAM;

        bar_grp(bar_id);   // BT[cur] built; Fs + stage[nxt] free

        // ---- stage scalars for next tile (overlaps GEMM) ----
        if (Tn < NTILES && tid_g < TILE_E) {
            const int bn  = Tn / NTILES_PER_B;
            const long en = (long)(Tn % NTILES_PER_B) * TILE_E;
            dist_s[nxt * TILE_E + tid_g] = dist[(size_t)bn * NE + en + tid_g];
            idx_s[nxt * TILE_E + tid_g]  = idx_j[en + tid_g];
            seg_s[nxt * TILE_E + tid_g]  = seg_i[en + tid_g];
        }

        // ---- GEMM on BT[cur]: F[e][c] = sum_k h1[e][k] * W2[k][c] ----
        {
            const uint32_t a_addr = sb + (uint32_t)(34816 + g * GRP_SIZE +
                                                    (cur ? GRP_BT1 : GRP_BT0)) + a_off;
            float acc[4][4];
            #pragma unroll
            for (int t = 0; t < 4; t++)
                acc[t][0] = acc[t][1] = acc[t][2] = acc[t][3] = 0.f;

            #pragma unroll
            for (int s = 0; s < 8; s++) {                  // K = 8 steps of 16
                uint32_t a0, a1, a2, a3;
                ldmat_x4(a0, a1, a2, a3, a_addr + s * 32);
                #pragma unroll
                for (int t2 = 0; t2 < 2; t2++) {           // 2 B ldmatrix -> 4 n-tiles
                    uint32_t b0, b1, b2r, b3;
                    ldmat_x4(b0, b1, b2r, b3, b_addr0 + t2 * 16 * BP + s * 32);
                    mma16816(acc[2 * t2],     a0, a1, a2, a3, b0,  b1);
                    mma16816(acc[2 * t2 + 1], a0, a1, a2, a3, b2r, b3);
                }
            }
            const int er = eq * 16 + lane / 4;
            const int cc = nq * 32 + 2 * (lane & 3);
            #pragma unroll
            for (int t = 0; t < 4; t++) {
                const int cn = cc + 8 * t;
                *(float2*)(Fs + er * FPITCH + cn)       = make_float2(acc[t][0], acc[t][1]);
                *(float2*)(Fs + (er + 8) * FPITCH + cn) = make_float2(acc[t][2], acc[t][3]);
            }
        }
        bar_grp(bar_id);   // Fs complete + staged scalars visible

        // ---- build BT[nxt] (L2-heavy; overlaps epilogue) ----
        if (Tn < NTILES)
            build_tile(grp + (nxt ? GRP_BT1 : GRP_BT0),
                       dist_s + nxt * TILE_E, gwid, lane, inv_h);

        // ---- epilogue: branch-free gather/ssp chunks + run-length scatter ----
        {
            const float* atomb = atom + (size_t)b * NATOMS * DCH;
            float*       outb  = out  + (size_t)b * NATOMS * DCH;
            const int*   isc   = idx_s + cur * TILE_E;
            const int*   ssc   = seg_s + cur * TILE_E;
            const int eb = q * 16;

            float gv[2][8];
            #pragma unroll
            for (int j = 0; j < 8; j++)
                gv[0][j] = atomb[(size_t)isc[eb + j] * DCH + ec];

            int   cseg = -1;
            float acc  = 0.f;
            #pragma unroll
            for (int ck = 0; ck < 2; ck++) {
                const int cb = ck & 1, nb = cb ^ 1;
                if (ck < 1) {
                    #pragma unroll
                    for (int j = 0; j < 8; j++)
                        gv[nb][j] = atomb[(size_t)isc[eb + 8 + j] * DCH + ec];
                }
                float msg[8];
                #pragma unroll
                for (int j = 0; j < 8; j++)
                    msg[j] = gv[cb][j] * ssp(Fs[(eb + ck * 8 + j) * FPITCH + ec] + b2c);
                #pragma unroll
                for (int j = 0; j < 8; j++) {
                    const int sg = ssc[eb + ck * 8 + j];
                    if (sg != cseg) {
                        if (cseg >= 0) atomicAdd(outb + (size_t)cseg * DCH + ec, acc);
                        cseg = sg;
                        acc = msg[j];
                    } else {
                        acc += msg[j];
                    }
                }
            }
            if (cseg >= 0) atomicAdd(outb + (size_t)cseg * DCH + ec, acc);
        }
    }
}

// ---------------- launch ----------------
extern "C" void kernel_launch(void* const* d_in, const int* in_sizes, int n_in,
                              void* d_out, int out_size) {
    const float* atom    = (const float*)d_in[0];
    const float* dist    = (const float*)d_in[1];
    const int*   idx_j   = (const int*)  d_in[2];
    const int*   seg_i   = (const int*)  d_in[3];
    const float* centers = (const float*)d_in[4];
    const float* gammav  = (const float*)d_in[5];
    const float* W1      = (const float*)d_in[6];
    const float* b1      = (const float*)d_in[7];
    const float* W2      = (const float*)d_in[8];
    const float* b2      = (const float*)d_in[9];
    float* out = (float*)d_out;
    (void)in_sizes; (void)n_in;

    cudaFuncSetAttribute(cfconv_mma_kernel,
                         cudaFuncAttributeMaxDynamicSharedMemorySize, SMEM_BYTES);

    build_prologue_kernel<<<TABN + 2, DCH>>>(centers, gammav, W1, b1, W2);
    cudaMemsetAsync(d_out, 0, (size_t)out_size * sizeof(float), 0);
    cfconv_mma_kernel<<<GRID, TPB, SMEM_BYTES>>>(atom, dist, idx_j, seg_i, b2, out);
}

// round 14
// speedup vs baseline: 8.8687x; 2.7210x over previous
#include <cuda_runtime.h>
#include <cuda_fp16.h>
#include <cstdint>

// ---------------- problem constants ----------------
#define NB      2
#define NATOMS  25000
#define NE      400000
#define DCH     128
#define NRBF    64
#define CUTOFF  15.0f
#define TABN    4096                     // lerp intervals for the filter table

#define GRID    592
#define TPB     256
#define WPB     (TPB/32)                 // 8
#define TOTAL_WARPS (GRID*WPB)           // 4736
#define WARPS_PER_B (TOTAL_WARPS/NB)     // 2368
#define CHUNK   172                      // 2368*172 = 407296 >= 400000, mult of 4

// distance -> FULL filter lookup table, f16:
//   ftab[i][c] = ssp( ssp(rbf(x_i)@W1 + b1) @ W2 + b2 )[c]
__device__ __half g_ftab[(TABN + 1) * DCH];    // ~1.05 MB, L2-resident

// ---------------- helpers ----------------
__device__ __forceinline__ float ssp(float x) {
    float ax = fabsf(x);
    return fmaxf(x, 0.f) + __logf(1.f + __expf(-ax)) - 0.69314718056f;
}
__device__ __forceinline__ void bar_named(int id, int cnt) {
    asm volatile("bar.sync %0, %1;" :: "r"(id), "r"(cnt) : "memory");
}

// ---------------- prologue: build the full-MLP filter table ----------------
// 148 blocks x 256 threads = 296 half-block streams over TABN+1 grid points.
// W1 (32KB) + W2 (64KB) staged in smem once per block.
#define PGRID 148
__global__ __launch_bounds__(256, 1)
void build_ftab_kernel(const float* __restrict__ centers,
                       const float* __restrict__ gammav,
                       const float* __restrict__ W1,
                       const float* __restrict__ b1,
                       const float* __restrict__ W2,
                       const float* __restrict__ b2) {
    extern __shared__ float sm[];
    float* W1s = sm;              // 8192 floats
    float* W2s = sm + 8192;       // 16384 floats
    float* stg = sm + 24576;      // [2][192] : rbf[64] + h1[128] per half

    const int tid = threadIdx.x;
    for (int i = tid; i < NRBF * DCH; i += 256) W1s[i] = W1[i];
    for (int i = tid; i < DCH * DCH;  i += 256) W2s[i] = W2[i];
    __syncthreads();

    const int half = tid >> 7;
    const int c    = tid & 127;
    const int bar  = 1 + half;
    float* rbf = stg + half * 192;
    float* h1  = rbf + 64;
    const float b1c = b1[c];
    const float b2c = b2[c];
    const float cc  = (c < NRBF) ? centers[c] : 0.f;
    const float gg  = (c < NRBF) ? gammav[c] : 0.f;

    for (int p = blockIdx.x * 2 + half; p <= TABN; p += 2 * PGRID) {
        const float x = (float)p * (CUTOFF / (float)TABN);
        if (c < NRBF) {
            float t = x - cc;
            rbf[c] = __expf(-gg * t * t);
        }
        bar_named(bar, 128);
        float a = b1c;
        #pragma unroll
        for (int k = 0; k < NRBF; k++)
            a = fmaf(rbf[k], W1s[k * DCH + c], a);
        h1[c] = ssp(a);
        bar_named(bar, 128);
        float a2 = b2c;
        #pragma unroll 8
        for (int k = 0; k < DCH; k++)
            a2 = fmaf(h1[k], W2s[k * DCH + c], a2);
        g_ftab[(size_t)p * DCH + c] = __float2half(ssp(a2));
        bar_named(bar, 128);   // protect rbf/h1 before next iteration
    }
}

// ---------------- main kernel: lerp filter + gather + run-length scatter ----------------
__global__ __launch_bounds__(TPB)
void cfconv_kernel(const float* __restrict__ atom,   // [B, N, D]
                   const float* __restrict__ dist,   // [B, E]
                   const int*   __restrict__ idx_j,  // [E]
                   const int*   __restrict__ seg_i,  // [E] sorted
                   float*       __restrict__ out)    // [B, N, D] zeroed
{
    const int wid  = threadIdx.x >> 5;
    const int lane = threadIdx.x & 31;
    const int gw   = blockIdx.x * WPB + wid;
    const int b    = gw / WARPS_PER_B;
    const long e0  = (long)(gw % WARPS_PER_B) * CHUNK;
    long e_end = e0 + CHUNK; if (e_end > NE) e_end = NE;

    const int c0 = lane * 4;
    const float inv_h = (float)TABN / CUTOFF;

    const float* distb = dist + (size_t)b * NE;
    const float* atomb = atom + (size_t)b * NATOMS * DCH;
    float*       outb  = out  + (size_t)b * NATOMS * DCH;

    int    cur  = -1;
    float4 racc = make_float4(0.f, 0.f, 0.f, 0.f);

    for (long base = e0; base < e_end; base += 4) {
        const int m = (int)((e_end - base) < 4 ? (e_end - base) : 4);

        uint2  tl[4], th[4];
        float4 gv[4];
        float  fr[4];
        int    sg[4];
        #pragma unroll
        for (int e = 0; e < 4; e++) {
            const long ge = base + (e < m ? e : m - 1);
            float xx = distb[ge] * inv_h;
            int   ix = (int)xx;
            ix = ix < 0 ? 0 : (ix > TABN - 1 ? TABN - 1 : ix);
            fr[e] = xx - (float)ix;
            const __half* rp = g_ftab + (size_t)ix * DCH + c0;
            tl[e] = *(const uint2*)rp;
            th[e] = *(const uint2*)(rp + DCH);
            gv[e] = *(const float4*)(atomb + (size_t)idx_j[ge] * DCH + c0);
            sg[e] = seg_i[ge];
        }

        #pragma unroll
        for (int e = 0; e < 4; e++) {
            if (e >= m) break;
            const float2 l0 = __half22float2(*(const __half2*)&tl[e].x);
            const float2 l1 = __half22float2(*(const __half2*)&tl[e].y);
            const float2 u0 = __half22float2(*(const __half2*)&th[e].x);
            const float2 u1 = __half22float2(*(const __half2*)&th[e].y);
            const float f = fr[e];
            float4 msg;
            msg.x = gv[e].x * fmaf(f, u0.x - l0.x, l0.x);
            msg.y = gv[e].y * fmaf(f, u0.y - l0.y, l0.y);
            msg.z = gv[e].z * fmaf(f, u1.x - l1.x, l1.x);
            msg.w = gv[e].w * fmaf(f, u1.y - l1.y, l1.y);
            if (sg[e] != cur) {
                if (cur >= 0) {
                    float* o = outb + (size_t)cur * DCH + c0;
                    atomicAdd(o + 0, racc.x);
                    atomicAdd(o + 1, racc.y);
                    atomicAdd(o + 2, racc.z);
                    atomicAdd(o + 3, racc.w);
                }
                cur  = sg[e];
                racc = msg;
            } else {
                racc.x += msg.x; racc.y += msg.y;
                racc.z += msg.z; racc.w += msg.w;
            }
        }
    }

    if (cur >= 0) {
        float* o = outb + (size_t)cur * DCH + c0;
        atomicAdd(o + 0, racc.x);
        atomicAdd(o + 1, racc.y);
        atomicAdd(o + 2, racc.z);
        atomicAdd(o + 3, racc.w);
    }
}

// ---------------- launch ----------------
extern "C" void kernel_launch(void* const* d_in, const int* in_sizes, int n_in,
                              void* d_out, int out_size) {
    const float* atom    = (const float*)d_in[0];
    const float* dist    = (const float*)d_in[1];
    const int*   idx_j   = (const int*)  d_in[2];
    const int*   seg_i   = (const int*)  d_in[3];
    const float* centers = (const float*)d_in[4];
    const float* gammav  = (const float*)d_in[5];
    const float* W1      = (const float*)d_in[6];
    const float* b1      = (const float*)d_in[7];
    const float* W2      = (const float*)d_in[8];
    const float* b2      = (const float*)d_in[9];
    float* out = (float*)d_out;
    (void)in_sizes; (void)n_in;

    const int psm = (8192 + 16384 + 2 * 192) * sizeof(float);   // ~99.8 KB
    cudaFuncSetAttribute(build_ftab_kernel,
                         cudaFuncAttributeMaxDynamicSharedMemorySize, psm);

    build_ftab_kernel<<<PGRID, 256, psm>>>(centers, gammav, W1, b1, W2, b2);
    cudaMemsetAsync(d_out, 0, (size_t)out_size * sizeof(float), 0);
    cfconv_kernel<<<GRID, TPB>>>(atom, dist, idx_j, seg_i, out);
}

// round 15
// speedup vs baseline: 9.5589x; 1.0778x over previous
#include <cuda_runtime.h>
#include <cuda_fp16.h>
#include <cstdint>

// ---------------- problem constants ----------------
#define NB      2
#define NATOMS  25000
#define NE      400000
#define DCH     128
#define NRBF    64
#define CUTOFF  15.0f
#define TABN    2048                     // lerp intervals for the filter table

#define GRID    592
#define TPB     256
#define WPB     (TPB/32)                 // 8
#define TOTAL_WARPS (GRID*WPB)           // 4736
#define WARPS_PER_B (TOTAL_WARPS/NB)     // 2368
#define CHUNK   172                      // 2368*172 >= 400000, mult of 4

// distance -> FULL filter lookup table, f16:
//   ftab[i][c] = ssp( ssp(rbf(x_i)@W1 + b1) @ W2 + b2 )[c]
__device__ __half g_ftab[(TABN + 1) * DCH];        // ~525 KB, L2/L1-resident
// atom features converted to f16 (halves gather traffic)
__device__ __half g_atom16[NB * NATOMS * DCH];     // 12.8 MB, L2-resident

// ---------------- helpers ----------------
__device__ __forceinline__ float ssp(float x) {
    float ax = fabsf(x);
    return fmaxf(x, 0.f) + __logf(1.f + __expf(-ax)) - 0.69314718056f;
}
__device__ __forceinline__ uint32_t pack_half2(float x, float y) {  // lo=x, hi=y
    uint32_t u;
    asm("cvt.rn.f16x2.f32 %0, %1, %2;" : "=r"(u) : "f"(y), "f"(x));
    return u;
}
__device__ __forceinline__ void bar_named(int id, int cnt) {
    asm volatile("bar.sync %0, %1;" :: "r"(id), "r"(cnt) : "memory");
}

// ---------------- prologue A: build the full-MLP filter table ----------------
#define PGRID 148
__global__ __launch_bounds__(256, 1)
void build_ftab_kernel(const float* __restrict__ centers,
                       const float* __restrict__ gammav,
                       const float* __restrict__ W1,
                       const float* __restrict__ b1,
                       const float* __restrict__ W2,
                       const float* __restrict__ b2) {
    extern __shared__ float sm[];
    float* W1s = sm;              // 8192 floats
    float* W2s = sm + 8192;       // 16384 floats
    float* stg = sm + 24576;      // [2][192] : rbf[64] + h1[128] per half

    const int tid = threadIdx.x;
    for (int i = tid; i < NRBF * DCH; i += 256) W1s[i] = W1[i];
    for (int i = tid; i < DCH * DCH;  i += 256) W2s[i] = W2[i];
    __syncthreads();

    const int half = tid >> 7;
    const int c    = tid & 127;
    const int bar  = 1 + half;
    float* rbf = stg + half * 192;
    float* h1  = rbf + 64;
    const float b1c = b1[c];
    const float b2c = b2[c];
    const float cc  = (c < NRBF) ? centers[c] : 0.f;
    const float gg  = (c < NRBF) ? gammav[c] : 0.f;

    for (int p = blockIdx.x * 2 + half; p <= TABN; p += 2 * PGRID) {
        const float x = (float)p * (CUTOFF / (float)TABN);
        if (c < NRBF) {
            float t = x - cc;
            rbf[c] = __expf(-gg * t * t);
        }
        bar_named(bar, 128);
        float a = b1c;
        #pragma unroll
        for (int k = 0; k < NRBF; k++)
            a = fmaf(rbf[k], W1s[k * DCH + c], a);
        h1[c] = ssp(a);
        bar_named(bar, 128);
        float a2 = b2c;
        #pragma unroll 8
        for (int k = 0; k < DCH; k++)
            a2 = fmaf(h1[k], W2s[k * DCH + c], a2);
        g_ftab[p * DCH + c] = __float2half(ssp(a2));
        bar_named(bar, 128);   // protect rbf/h1 before next iteration
    }
}

// ---------------- prologue B: atom features f32 -> f16 ----------------
__global__ __launch_bounds__(256)
void conv_atom_kernel(const float* __restrict__ atom) {
    const int total = NB * NATOMS * DCH / 4;   // float4 count
    for (int i = blockIdx.x * blockDim.x + threadIdx.x; i < total;
         i += gridDim.x * blockDim.x) {
        const float4 v = ((const float4*)atom)[i];
        uint2 u;
        u.x = pack_half2(v.x, v.y);
        u.y = pack_half2(v.z, v.w);
        ((uint2*)g_atom16)[i] = u;
    }
}

// ---------------- main kernel: lerp filter + f16 gather + run-length scatter ----------------
__global__ __launch_bounds__(TPB, 5)
void cfconv_kernel(const float* __restrict__ dist,   // [B, E]
                   const int*   __restrict__ idx_j,  // [E]
                   const int*   __restrict__ seg_i,  // [E] sorted
                   float*       __restrict__ out)    // [B, N, D] zeroed
{
    const int wid  = threadIdx.x >> 5;
    const int lane = threadIdx.x & 31;
    const int gw   = blockIdx.x * WPB + wid;
    const int b    = gw / WARPS_PER_B;
    const int e0   = (gw % WARPS_PER_B) * CHUNK;
    int e_end = e0 + CHUNK; if (e_end > NE) e_end = NE;

    const int c0 = lane * 4;
    const float inv_h = (float)TABN / CUTOFF;

    const float*  distb  = dist + b * NE;
    const __half* atomb  = g_atom16 + (uint32_t)b * (NATOMS * DCH);
    float*        outb   = out + (uint32_t)b * (NATOMS * DCH);

    int    cur  = -1;
    float4 racc = make_float4(0.f, 0.f, 0.f, 0.f);

    for (int base = e0; base < e_end; base += 4) {
        const int m = (e_end - base) < 4 ? (e_end - base) : 4;

        uint2 tl[4], th[4], gv[4];
        float fr[4];
        int   sg[4];
        #pragma unroll
        for (int e = 0; e < 4; e++) {
            const int ge = base + (e < m ? e : m - 1);
            float xx = distb[ge] * inv_h;
            int   ix = (int)xx;
            ix = ix < 0 ? 0 : (ix > TABN - 1 ? TABN - 1 : ix);
            fr[e] = xx - (float)ix;
            const __half* rp = g_ftab + ix * DCH + c0;
            tl[e] = *(const uint2*)rp;
            th[e] = *(const uint2*)(rp + DCH);
            gv[e] = *(const uint2*)(atomb + (uint32_t)idx_j[ge] * DCH + c0);
            sg[e] = seg_i[ge];
        }

        #pragma unroll
        for (int e = 0; e < 4; e++) {
            if (e >= m) break;
            const float2 l0 = __half22float2(*(const __half2*)&tl[e].x);
            const float2 l1 = __half22float2(*(const __half2*)&tl[e].y);
            const float2 u0 = __half22float2(*(const __half2*)&th[e].x);
            const float2 u1 = __half22float2(*(const __half2*)&th[e].y);
            const float2 a0 = __half22float2(*(const __half2*)&gv[e].x);
            const float2 a1 = __half22float2(*(const __half2*)&gv[e].y);
            const float f = fr[e];
            float4 msg;
            msg.x = a0.x * fmaf(f, u0.x - l0.x, l0.x);
            msg.y = a0.y * fmaf(f, u0.y - l0.y, l0.y);
            msg.z = a1.x * fmaf(f, u1.x - l1.x, l1.x);
            msg.w = a1.y * fmaf(f, u1.y - l1.y, l1.y);
            if (sg[e] != cur) {
                if (cur >= 0) {
                    float* o = outb + (uint32_t)cur * DCH + c0;
                    atomicAdd(o + 0, racc.x);
                    atomicAdd(o + 1, racc.y);
                    atomicAdd(o + 2, racc.z);
                    atomicAdd(o + 3, racc.w);
                }
                cur  = sg[e];
                racc = msg;
            } else {
                racc.x += msg.x; racc.y += msg.y;
                racc.z += msg.z; racc.w += msg.w;
            }
        }
    }

    if (cur >= 0) {
        float* o = outb + (uint32_t)cur * DCH + c0;
        atomicAdd(o + 0, racc.x);
        atomicAdd(o + 1, racc.y);
        atomicAdd(o + 2, racc.z);
        atomicAdd(o + 3, racc.w);
    }
}

// ---------------- launch ----------------
extern "C" void kernel_launch(void* const* d_in, const int* in_sizes, int n_in,
                              void* d_out, int out_size) {
    const float* atom    = (const float*)d_in[0];
    const float* dist    = (const float*)d_in[1];
    const int*   idx_j   = (const int*)  d_in[2];
    const int*   seg_i   = (const int*)  d_in[3];
    const float* centers = (const float*)d_in[4];
    const float* gammav  = (const float*)d_in[5];
    const float* W1      = (const float*)d_in[6];
    const float* b1      = (const float*)d_in[7];
    const float* W2      = (const float*)d_in[8];
    const float* b2      = (const float*)d_in[9];
    float* out = (float*)d_out;
    (void)in_sizes; (void)n_in;

    const int psm = (8192 + 16384 + 2 * 192) * sizeof(float);   // ~99.8 KB
    cudaFuncSetAttribute(build_ftab_kernel,
                         cudaFuncAttributeMaxDynamicSharedMemorySize, psm);

    build_ftab_kernel<<<PGRID, 256, psm>>>(centers, gammav, W1, b1, W2, b2);
    conv_atom_kernel<<<GRID, 256>>>(atom);
    cudaMemsetAsync(d_out, 0, (size_t)out_size * sizeof(float), 0);
    cfconv_kernel<<<GRID, TPB>>>(dist, idx_j, seg_i, out);
}

// round 16
// speedup vs baseline: 9.7415x; 1.0191x over previous
#include <cuda_runtime.h>
#include <cuda_fp16.h>
#include <cstdint>

// ---------------- problem constants ----------------
#define NB      2
#define NATOMS  25000
#define NE      400000
#define DCH     128
#define NRBF    64
#define CUTOFF  15.0f
#define TABN    2048                     // lerp intervals

#define GRID    592
#define TPB     256
#define WPB     (TPB/32)                 // 8
#define TOTAL_WARPS (GRID*WPB)           // 4736
#define WARPS_PER_B (TOTAL_WARPS/NB)     // 2368
#define CHUNK   172                      // 2368*172 >= 400000, mult of 4

// pair-interleaved filter table: g_ftab2[i*DCH+c] = half2(f[i][c], f[i+1][c])
__device__ uint32_t g_ftab2[TABN * DCH];           // 1.05 MB, L2-resident
// atom features in f16
__device__ __half   g_atom16[NB * NATOMS * DCH];   // 12.8 MB

// ---------------- helpers ----------------
__device__ __forceinline__ float ssp(float x) {
    float ax = fabsf(x);
    return fmaxf(x, 0.f) + __logf(1.f + __expf(-ax)) - 0.69314718056f;
}
__device__ __forceinline__ uint32_t pack_half2(float x, float y) {  // lo=x, hi=y
    uint32_t u;
    asm("cvt.rn.f16x2.f32 %0, %1, %2;" : "=r"(u) : "f"(y), "f"(x));
    return u;
}
__device__ __forceinline__ void bar_named(int id, int cnt) {
    asm volatile("bar.sync %0, %1;" :: "r"(id), "r"(cnt) : "memory");
}

// ---------------- merged prologue ----------------
// blocks [0,148)    : build ftab, 4 independent 128-thread streams per block
// blocks [148,444)  : atom f32->f16 conversion + output zeroing (streaming)
#define PGRID   148
#define NAUX    296
#define PTPB    512
#define PSM_BYTES ((8192 + 16384 + 4 * 192) * 4)   // W1s + W2s + 4 stage areas

__global__ __launch_bounds__(PTPB, 1)
void prologue_kernel(const float* __restrict__ centers,
                     const float* __restrict__ gammav,
                     const float* __restrict__ W1,
                     const float* __restrict__ b1,
                     const float* __restrict__ W2,
                     const float* __restrict__ b2,
                     const float* __restrict__ atom,
                     float*       __restrict__ out) {
    const int tid = threadIdx.x;

    if (blockIdx.x >= PGRID) {
        // ---- aux role: convert atoms + zero output ----
        const int bid = blockIdx.x - PGRID;
        const int total4 = NB * NATOMS * DCH / 4;      // 1.6M float4
        for (int i = bid * PTPB + tid; i < total4; i += NAUX * PTPB) {
            const float4 v = ((const float4*)atom)[i];
            uint2 u;
            u.x = pack_half2(v.x, v.y);
            u.y = pack_half2(v.z, v.w);
            ((uint2*)g_atom16)[i] = u;
        }
        float4 z = make_float4(0.f, 0.f, 0.f, 0.f);
        for (int i = bid * PTPB + tid; i < total4; i += NAUX * PTPB)
            ((float4*)out)[i] = z;
        return;
    }

    // ---- ftab role ----
    extern __shared__ float sm[];
    float* W1s = sm;              // 8192 floats
    float* W2s = sm + 8192;       // 16384 floats
    float* stg = sm + 24576;      // [4][192] : rbf[64] + h1[128] per stream

    for (int i = tid; i < NRBF * DCH; i += PTPB) W1s[i] = W1[i];
    for (int i = tid; i < DCH * DCH;  i += PTPB) W2s[i] = W2[i];
    __syncthreads();

    const int strm = tid >> 7;            // 0..3
    const int c    = tid & 127;
    const int bar  = 1 + strm;
    float* rbf = stg + strm * 192;
    float* h1  = rbf + 64;
    const float b1c = b1[c];
    const float b2c = b2[c];
    const float cc  = (c < NRBF) ? centers[c] : 0.f;
    const float gg  = (c < NRBF) ? gammav[c] : 0.f;

    __half* ft = (__half*)g_ftab2;
    for (int p = blockIdx.x * 4 + strm; p <= TABN; p += 4 * PGRID) {
        const float x = (float)p * (CUTOFF / (float)TABN);
        if (c < NRBF) {
            float t = x - cc;
            rbf[c] = __expf(-gg * t * t);
        }
        bar_named(bar, 128);
        float a = b1c;
        #pragma unroll
        for (int k = 0; k < NRBF; k++)
            a = fmaf(rbf[k], W1s[k * DCH + c], a);
        h1[c] = ssp(a);
        bar_named(bar, 128);
        float a2 = b2c;
        #pragma unroll 8
        for (int k = 0; k < DCH; k++)
            a2 = fmaf(h1[k], W2s[k * DCH + c], a2);
        const __half v = __float2half(ssp(a2));
        if (p < TABN) ft[(p * DCH + c) * 2 + 0] = v;          // lo slot of row p
        if (p > 0)    ft[((p - 1) * DCH + c) * 2 + 1] = v;    // hi slot of row p-1
        bar_named(bar, 128);   // protect rbf/h1 before next iteration
    }
}

// ---------------- main kernel: paired-lerp filter + f16 gather + run-length scatter ----------------
__global__ __launch_bounds__(TPB, 5)
void cfconv_kernel(const float* __restrict__ dist,   // [B, E]
                   const int*   __restrict__ idx_j,  // [E]
                   const int*   __restrict__ seg_i,  // [E] sorted
                   float*       __restrict__ out)    // [B, N, D] zeroed
{
    const int wid  = threadIdx.x >> 5;
    const int lane = threadIdx.x & 31;
    const int gw   = blockIdx.x * WPB + wid;
    const int b    = gw / WARPS_PER_B;
    const int e0   = (gw % WARPS_PER_B) * CHUNK;
    int e_end = e0 + CHUNK; if (e_end > NE) e_end = NE;

    const int c0 = lane * 4;
    const float inv_h = (float)TABN / CUTOFF;

    const float*  distb = dist + b * NE;
    const __half* atomb = g_atom16 + (uint32_t)b * (NATOMS * DCH);
    float*        outb  = out + (uint32_t)b * (NATOMS * DCH);

    int    cur  = -1;
    float4 racc = make_float4(0.f, 0.f, 0.f, 0.f);

    for (int base = e0; base < e_end; base += 4) {
        const int m = (e_end - base) < 4 ? (e_end - base) : 4;

        uint4 tp[4];
        uint2 gv[4];
        float fr[4];
        int   sg[4];
        #pragma unroll
        for (int e = 0; e < 4; e++) {
            const int ge = base + (e < m ? e : m - 1);
            float xx = distb[ge] * inv_h;
            int   ix = (int)xx;
            ix = ix < 0 ? 0 : (ix > TABN - 1 ? TABN - 1 : ix);
            fr[e] = xx - (float)ix;
            tp[e] = *(const uint4*)(g_ftab2 + ix * DCH + c0);
            gv[e] = *(const uint2*)(atomb + (uint32_t)idx_j[ge] * DCH + c0);
            sg[e] = seg_i[ge];
        }

        #pragma unroll
        for (int e = 0; e < 4; e++) {
            if (e >= m) break;
            // each uint32 = (lo = f[ix][c], hi = f[ix+1][c])
            const float2 p0 = __half22float2(*(const __half2*)&tp[e].x);
            const float2 p1 = __half22float2(*(const __half2*)&tp[e].y);
            const float2 p2 = __half22float2(*(const __half2*)&tp[e].z);
            const float2 p3 = __half22float2(*(const __half2*)&tp[e].w);
            const float2 a0 = __half22float2(*(const __half2*)&gv[e].x);
            const float2 a1 = __half22float2(*(const __half2*)&gv[e].y);
            const float f = fr[e];
            float4 msg;
            msg.x = a0.x * fmaf(f, p0.y - p0.x, p0.x);
            msg.y = a0.y * fmaf(f, p1.y - p1.x, p1.x);
            msg.z = a1.x * fmaf(f, p2.y - p2.x, p2.x);
            msg.w = a1.y * fmaf(f, p3.y - p3.x, p3.x);
            if (sg[e] != cur) {
                if (cur >= 0) {
                    float* o = outb + (uint32_t)cur * DCH + c0;
                    atomicAdd(o + 0, racc.x);
                    atomicAdd(o + 1, racc.y);
                    atomicAdd(o + 2, racc.z);
                    atomicAdd(o + 3, racc.w);
                }
                cur  = sg[e];
                racc = msg;
            } else {
                racc.x += msg.x; racc.y += msg.y;
                racc.z += msg.z; racc.w += msg.w;
            }
        }
    }

    if (cur >= 0) {
        float* o = outb + (uint32_t)cur * DCH + c0;
        atomicAdd(o + 0, racc.x);
        atomicAdd(o + 1, racc.y);
        atomicAdd(o + 2, racc.z);
        atomicAdd(o + 3, racc.w);
    }
}

// ---------------- launch ----------------
extern "C" void kernel_launch(void* const* d_in, const int* in_sizes, int n_in,
                              void* d_out, int out_size) {
    const float* atom    = (const float*)d_in[0];
    const float* dist    = (const float*)d_in[1];
    const int*   idx_j   = (const int*)  d_in[2];
    const int*   seg_i   = (const int*)  d_in[3];
    const float* centers = (const float*)d_in[4];
    const float* gammav  = (const float*)d_in[5];
    const float* W1      = (const float*)d_in[6];
    const float* b1      = (const float*)d_in[7];
    const float* W2      = (const float*)d_in[8];
    const float* b2      = (const float*)d_in[9];
    float* out = (float*)d_out;
    (void)in_sizes; (void)n_in;

    cudaFuncSetAttribute(prologue_kernel,
                         cudaFuncAttributeMaxDynamicSharedMemorySize, PSM_BYTES);

    prologue_kernel<<<PGRID + NAUX, PTPB, PSM_BYTES>>>(
        centers, gammav, W1, b1, W2, b2, atom, out);
    cfconv_kernel<<<GRID, TPB>>>(dist, idx_j, seg_i, out);
}